// round 9
// baseline (speedup 1.0000x reference)
#include <cuda_runtime.h>
#include <cuda_bf16.h>
#include <math.h>
#include <stdint.h>

// ----------------------------------------------------------------------------
// k' = k(0.8+0.28g) + 0.52 g v ; v' = 0.8 v + 0.2 u_t ; g = g(k^2+u^2).
// Out: tanh(k_final).   (64-pt GL quadrature folded into host-built table.)
//
// 1) Contraction: only LAST W=512 steps from (0,0) matter (validated R3/R4).
// 2) Host-built linearized table g ~ a_i + b_i*s (2048 entries over [0,24]),
//    passed by value as 16KB kernel param.
// 3) Picard + affine warp scan (32 thr x 16 steps, 8 sweeps) — validated R7/R8
//    (rel_err bit-identical to serial reference path).
// 4) NEW (R9): 16 warps cooperatively stage the param table const->SMEM to
//    parallelize LDC miss latency (R8's single-warp copy was the floor);
//    warp 0 alone computes after one __syncthreads.
// ----------------------------------------------------------------------------

#define GLN 64
#define NTAB 2048
#define S_MAX 24.0f
#define INV_DS ((float)NTAB / S_MAX)
#define W 512
#define TPB 512
#define CHUNK 16
#define NSWEEP 8

struct TabParam { float2 e[NTAB]; };   // 16384 bytes, by value

__device__ __forceinline__ void warp_scan_affine(float& A, float& B, int lane) {
    #pragma unroll
    for (int off = 1; off < 32; off <<= 1) {
        float Ag = __shfl_up_sync(0xFFFFFFFFu, A, off);
        float Bg = __shfl_up_sync(0xFFFFFFFFu, B, off);
        if (lane >= off) { B = fmaf(A, Bg, B); A *= Ag; }
    }
}

__global__ void __launch_bounds__(TPB, 1)
run_kernel(TabParam tp, const float* __restrict__ u,
           float* __restrict__ out, int n) {
    __shared__ float2 tab[NTAB];   // 16 KB
    const int tid  = threadIdx.x;
    const int lane = tid & 31;

    // ALL 16 warps stage the table (parallelize const-cache misses):
    // NTAB/2 = 1024 float4 loads, 2 per thread.
    {
        const float4* src = (const float4*)tp.e;
        float4* dst = (float4*)tab;
        dst[tid]       = src[tid];
        dst[tid + 512] = src[tid + 512];
    }
    __syncthreads();
    if (tid >= 32) return;          // warps 1..15 done

    // ---- warp 0 only below --------------------------------------------------
    float su2[CHUNK], cj[CHUNK], k[CHUNK];

    const int base = n - W + lane * CHUNK;
    #pragma unroll
    for (int j = 0; j < CHUNK; ++j) {
        int gi = base + j;
        float x = (gi >= 0) ? u[gi] : 0.0f;   // zero-pad front (exact)
        cj[j] = x;                             // stash u temporarily
        su2[j] = x * x;
        k[j] = 0.0f;
    }

    // ---- v scan: v_t = 0.8 v_{t-1} + 0.2 u_t, v_0 = 0; cj = 0.52*v_{t-1} ---
    {
        float B = 0.0f;
        float Bp[CHUNK];                       // inclusive B prefix (A = 0.8^j)
        #pragma unroll
        for (int j = 0; j < CHUNK; ++j) {
            B = fmaf(0.8f, B, 0.2f * cj[j]);
            Bp[j] = B;
        }
        float As = 0.0281474976710656f;        // 0.8^16
        float Bs = B;
        warp_scan_affine(As, Bs, lane);
        float vstart = __shfl_up_sync(0xFFFFFFFFu, Bs, 1);
        if (lane == 0) vstart = 0.0f;
        float Aj = 1.0f;
        cj[0] = 0.52f * vstart;
        #pragma unroll
        for (int j = 1; j < CHUNK; ++j) {
            Aj *= 0.8f;                        // 0.8^j
            cj[j] = 0.52f * fmaf(Aj, vstart, Bp[j - 1]);
        }
    }

    unsigned sbase = (unsigned)__cvta_generic_to_shared(tab);
    const unsigned OFFC = sbase - 0x58000000u;   // sbase - 8*0x4B000000 mod 2^32
    const float MAGIC = 8388608.0f;              // 2^23 (round-to-nearest)
    const float TMAX  = MAGIC + (float)(NTAB - 1);

    float klast = 0.0f;

    #pragma unroll 1
    for (int sw = 0; sw < NSWEEP; ++sw) {
        float knb = __shfl_up_sync(0xFFFFFFFFu, klast, 1);
        if (lane == 0) knb = 0.0f;

        // fused: lookup + affine coeff + local inclusive compose
        float Al[CHUNK], Bl[CHUNK];
        float A = 1.0f, B = 0.0f;
        #pragma unroll
        for (int j = 0; j < CHUNK; ++j) {
            float kp = (j == 0) ? knb : k[j - 1];
            float s  = fmaf(kp, kp, su2[j]);
            float tt = fminf(fmaf(s, INV_DS, MAGIC), TMAX);
            unsigned addr = __float_as_uint(tt) * 8u + OFFC;
            float a_, b_;
            asm("ld.shared.v2.f32 {%0,%1},[%2];"
                : "=f"(a_), "=f"(b_) : "r"(addr));
            float g  = fmaf(b_, s, a_);
            float at = fmaf(0.28f, g, 0.8f);
            float bt = g * cj[j];
            B = fmaf(at, B, bt);
            A = at * A;
            Al[j] = A; Bl[j] = B;
        }

        // warp scan + exclusive start (k_0 = 0 -> kstart = B_excl)
        float As = A, Bs = B;
        warp_scan_affine(As, Bs, lane);
        float kstart = __shfl_up_sync(0xFFFFFFFFu, Bs, 1);
        if (lane == 0) kstart = 0.0f;

        // rebuild trajectory (independent FMAs)
        #pragma unroll
        for (int j = 0; j < CHUNK; ++j)
            k[j] = fmaf(Al[j], kstart, Bl[j]);
        klast = k[CHUNK - 1];
    }

    if (lane == 31) *out = tanhf(k[CHUNK - 1]);
}

// ---------------------------------------------------------------------------
// Host: Gauss-Legendre n=64 + table build (double precision, input-indep).
// ---------------------------------------------------------------------------
static void host_leggauss64(double* x, double* w) {
    const int n = GLN;
    const double PI = 3.14159265358979323846;
    for (int i = 0; i < n; ++i) {
        double xi = cos(PI * (i + 0.75) / (n + 0.5));
        double p0 = 1.0, p1 = 0.0, pp = 1.0;
        for (int it = 0; it < 100; ++it) {
            p0 = 1.0; p1 = 0.0;
            for (int j = 1; j <= n; ++j) {
                double p2 = p1; p1 = p0;
                p0 = ((2.0 * j - 1.0) * xi * p1 - (j - 1.0) * p2) / j;
            }
            pp = n * (xi * p0 - p1) / (xi * xi - 1.0);
            double dx = p0 / pp;
            xi -= dx;
            if (fabs(dx) < 1e-15) break;
        }
        p0 = 1.0; p1 = 0.0;
        for (int j = 1; j <= n; ++j) {
            double p2 = p1; p1 = p0;
            p0 = ((2.0 * j - 1.0) * xi * p1 - (j - 1.0) * p2) / j;
        }
        pp = n * (xi * p0 - p1) / (xi * xi - 1.0);
        x[i] = xi;
        w[i] = 2.0 / ((1.0 - xi * xi) * pp * pp);
    }
}

static double host_g(double s, const double* X, const double* EW) {
    double d = sqrt(s);
    double acc = 0.0;
    for (int q = 0; q < GLN; ++q) {
        double th = tanh(d * X[q]);
        acc += EW[q] * (1.0 - th * th);
    }
    return acc * 0.15915494309189535;   // 1/(2*pi)
}

static void host_build_table(TabParam* tp) {
    double x[GLN], wq[GLN], X[GLN], EW[GLN];
    host_leggauss64(x, wq);
    for (int q = 0; q < GLN; ++q) {
        X[q]  = x[q] * 5.0;
        EW[q] = wq[q] * 5.0 * exp(-X[q] * X[q] * 0.5);
    }
    const double ds = (double)S_MAX / (double)NTAB;
    for (int i = 0; i < NTAB; ++i) {
        double s  = i * ds;
        double h  = 0.5 * ds;
        double sl = (s - h > 0.0) ? (s - h) : 0.0;
        double sh = s + h;
        double g0 = host_g(s,  X, EW);
        double gm = host_g(sl, X, EW);
        double gp = host_g(sh, X, EW);
        double bb = (gp - gm) / (sh - sl);
        tp->e[i].x = (float)(g0 - bb * s);
        tp->e[i].y = (float)bb;
    }
}

// ---------------------------------------------------------------------------
extern "C" void kernel_launch(void* const* d_in, const int* in_sizes, int n_in,
                              void* d_out, int out_size) {
    (void)n_in; (void)out_size;
    const float* u = (const float*)d_in[0];
    float* out = (float*)d_out;
    int n = in_sizes[0];

    static TabParam tp;
    host_build_table(&tp);   // deterministic, host-side, input-independent

    run_kernel<<<1, TPB>>>(tp, u, out, n);
}

// round 10
// speedup vs baseline: 1.3060x; 1.3060x over previous
#include <cuda_runtime.h>
#include <cuda_bf16.h>
#include <math.h>
#include <stdint.h>

// ----------------------------------------------------------------------------
// k' = k(0.8+0.28g) + 0.52 g v ; v' = 0.8 v + 0.2 u_t ; g = g(k^2+u^2).
// Out: tanh(k_final).   (64-pt GL quadrature folded into host-built table.)
//
// 1) Contraction: only LAST W=512 steps from (0,0) matter (validated R3/R4).
// 2) Host-built linearized table g ~ a_i + b_i*s (2048 entries over [0,24]),
//    passed by value as a 16KB kernel parameter.
// 3) Picard + affine warp scan (32 thr x 16 steps, 8 sweeps) — validated
//    R7/R8/R9 (rel_err bit-identical to serial reference path).
// 4) NEW (R10): the 16KB param lives on the CONSTANT path whose misses
//    serialize PER-SM (R8 vs R9 evidence). Kernel A spreads the param->global
//    copy across 256 tiny blocks (1 cache line each, ~2 misses/SM). Kernel B
//    stages the table from L2-hot GLOBAL via LDG (deep MLP) and computes.
// ----------------------------------------------------------------------------

#define GLN 64
#define NTAB 2048
#define S_MAX 24.0f
#define INV_DS ((float)NTAB / S_MAX)
#define W 512
#define TPB 512
#define CHUNK 16
#define NSWEEP 8

struct TabParam { float2 e[NTAB]; };   // 16384 bytes, by value

__device__ float2 g_tab_dev[NTAB];     // global staging of the table

// ---------------------------------------------------------------------------
// Kernel A: param(const bank) -> global, one 64B line per block, many SMs.
// ---------------------------------------------------------------------------
__global__ void __launch_bounds__(8, 1)
copy_tab_kernel(TabParam tp) {
    int i = blockIdx.x * 8 + threadIdx.x;   // 8 float2 = 64 B per block
    g_tab_dev[i] = tp.e[i];
}

// ---------------------------------------------------------------------------
__device__ __forceinline__ void warp_scan_affine(float& A, float& B, int lane) {
    #pragma unroll
    for (int off = 1; off < 32; off <<= 1) {
        float Ag = __shfl_up_sync(0xFFFFFFFFu, A, off);
        float Bg = __shfl_up_sync(0xFFFFFFFFu, B, off);
        if (lane >= off) { B = fmaf(A, Bg, B); A *= Ag; }
    }
}

// ---------------------------------------------------------------------------
// Kernel B: stage table global->SMEM (LDG, 16 warps), warp 0 computes.
// ---------------------------------------------------------------------------
__global__ void __launch_bounds__(TPB, 1)
run_kernel(const float* __restrict__ u, float* __restrict__ out, int n) {
    __shared__ float2 tab[NTAB];   // 16 KB
    const int tid  = threadIdx.x;
    const int lane = tid & 31;

    // warp 0 issues its u loads FIRST so DRAM latency overlaps table staging
    float su2[CHUNK], cj[CHUNK], k[CHUNK];
    if (tid < 32) {
        const int base = n - W + lane * CHUNK;
        #pragma unroll
        for (int j = 0; j < CHUNK; ++j) {
            int gi = base + j;
            float x = (gi >= 0) ? u[gi] : 0.0f;   // zero-pad front (exact)
            cj[j] = x;                             // stash u temporarily
            su2[j] = x * x;
            k[j] = 0.0f;
        }
    }

    // all 16 warps stage the table from L2-hot global (deep-MLP LDG path)
    {
        const float4* src = (const float4*)g_tab_dev;
        float4* dst = (float4*)tab;
        dst[tid]       = src[tid];
        dst[tid + 512] = src[tid + 512];
    }
    __syncthreads();
    if (tid >= 32) return;

    // ---- v scan: v_t = 0.8 v_{t-1} + 0.2 u_t, v_0 = 0; cj = 0.52*v_{t-1} ---
    {
        float B = 0.0f;
        float Bp[CHUNK];                       // inclusive B prefix (A = 0.8^j)
        #pragma unroll
        for (int j = 0; j < CHUNK; ++j) {
            B = fmaf(0.8f, B, 0.2f * cj[j]);
            Bp[j] = B;
        }
        float As = 0.0281474976710656f;        // 0.8^16
        float Bs = B;
        warp_scan_affine(As, Bs, lane);
        float vstart = __shfl_up_sync(0xFFFFFFFFu, Bs, 1);
        if (lane == 0) vstart = 0.0f;
        float Aj = 1.0f;
        cj[0] = 0.52f * vstart;
        #pragma unroll
        for (int j = 1; j < CHUNK; ++j) {
            Aj *= 0.8f;                        // 0.8^j
            cj[j] = 0.52f * fmaf(Aj, vstart, Bp[j - 1]);
        }
    }

    unsigned sbase = (unsigned)__cvta_generic_to_shared(tab);
    const unsigned OFFC = sbase - 0x58000000u;   // sbase - 8*0x4B000000 mod 2^32
    const float MAGIC = 8388608.0f;              // 2^23 (round-to-nearest)
    const float TMAX  = MAGIC + (float)(NTAB - 1);

    float klast = 0.0f;

    #pragma unroll 1
    for (int sw = 0; sw < NSWEEP; ++sw) {
        float knb = __shfl_up_sync(0xFFFFFFFFu, klast, 1);
        if (lane == 0) knb = 0.0f;

        // fused: lookup + affine coeff + local inclusive compose
        float Al[CHUNK], Bl[CHUNK];
        float A = 1.0f, B = 0.0f;
        #pragma unroll
        for (int j = 0; j < CHUNK; ++j) {
            float kp = (j == 0) ? knb : k[j - 1];
            float s  = fmaf(kp, kp, su2[j]);
            float tt = fminf(fmaf(s, INV_DS, MAGIC), TMAX);
            unsigned addr = __float_as_uint(tt) * 8u + OFFC;
            float a_, b_;
            asm("ld.shared.v2.f32 {%0,%1},[%2];"
                : "=f"(a_), "=f"(b_) : "r"(addr));
            float g  = fmaf(b_, s, a_);
            float at = fmaf(0.28f, g, 0.8f);
            float bt = g * cj[j];
            B = fmaf(at, B, bt);
            A = at * A;
            Al[j] = A; Bl[j] = B;
        }

        // warp scan + exclusive start (k_0 = 0 -> kstart = B_excl)
        float As = A, Bs = B;
        warp_scan_affine(As, Bs, lane);
        float kstart = __shfl_up_sync(0xFFFFFFFFu, Bs, 1);
        if (lane == 0) kstart = 0.0f;

        // rebuild trajectory (independent FMAs)
        #pragma unroll
        for (int j = 0; j < CHUNK; ++j)
            k[j] = fmaf(Al[j], kstart, Bl[j]);
        klast = k[CHUNK - 1];
    }

    if (lane == 31) *out = tanhf(k[CHUNK - 1]);
}

// ---------------------------------------------------------------------------
// Host: Gauss-Legendre n=64 + table build (double precision, input-indep).
// ---------------------------------------------------------------------------
static void host_leggauss64(double* x, double* w) {
    const int n = GLN;
    const double PI = 3.14159265358979323846;
    for (int i = 0; i < n; ++i) {
        double xi = cos(PI * (i + 0.75) / (n + 0.5));
        double p0 = 1.0, p1 = 0.0, pp = 1.0;
        for (int it = 0; it < 100; ++it) {
            p0 = 1.0; p1 = 0.0;
            for (int j = 1; j <= n; ++j) {
                double p2 = p1; p1 = p0;
                p0 = ((2.0 * j - 1.0) * xi * p1 - (j - 1.0) * p2) / j;
            }
            pp = n * (xi * p0 - p1) / (xi * xi - 1.0);
            double dx = p0 / pp;
            xi -= dx;
            if (fabs(dx) < 1e-15) break;
        }
        p0 = 1.0; p1 = 0.0;
        for (int j = 1; j <= n; ++j) {
            double p2 = p1; p1 = p0;
            p0 = ((2.0 * j - 1.0) * xi * p1 - (j - 1.0) * p2) / j;
        }
        pp = n * (xi * p0 - p1) / (xi * xi - 1.0);
        x[i] = xi;
        w[i] = 2.0 / ((1.0 - xi * xi) * pp * pp);
    }
}

static double host_g(double s, const double* X, const double* EW) {
    double d = sqrt(s);
    double acc = 0.0;
    for (int q = 0; q < GLN; ++q) {
        double th = tanh(d * X[q]);
        acc += EW[q] * (1.0 - th * th);
    }
    return acc * 0.15915494309189535;   // 1/(2*pi)
}

static void host_build_table(TabParam* tp) {
    double x[GLN], wq[GLN], X[GLN], EW[GLN];
    host_leggauss64(x, wq);
    for (int q = 0; q < GLN; ++q) {
        X[q]  = x[q] * 5.0;
        EW[q] = wq[q] * 5.0 * exp(-X[q] * X[q] * 0.5);
    }
    const double ds = (double)S_MAX / (double)NTAB;
    for (int i = 0; i < NTAB; ++i) {
        double s  = i * ds;
        double h  = 0.5 * ds;
        double sl = (s - h > 0.0) ? (s - h) : 0.0;
        double sh = s + h;
        double g0 = host_g(s,  X, EW);
        double gm = host_g(sl, X, EW);
        double gp = host_g(sh, X, EW);
        double bb = (gp - gm) / (sh - sl);
        tp->e[i].x = (float)(g0 - bb * s);
        tp->e[i].y = (float)bb;
    }
}

// ---------------------------------------------------------------------------
extern "C" void kernel_launch(void* const* d_in, const int* in_sizes, int n_in,
                              void* d_out, int out_size) {
    (void)n_in; (void)out_size;
    const float* u = (const float*)d_in[0];
    float* out = (float*)d_out;
    int n = in_sizes[0];

    static TabParam tp;
    host_build_table(&tp);   // deterministic, host-side, input-independent

    copy_tab_kernel<<<NTAB / 8, 8>>>(tp);     // param -> global, spread wide
    run_kernel<<<1, TPB>>>(u, out, n);        // global(L2) -> SMEM, compute
}